// round 15
// baseline (speedup 1.0000x reference)
#include <cuda_runtime.h>
#include <cstdint>

// Problem constants
#define VOCAB  8192
#define NTOK   16384          // B*T = 8*2048
#define TI     128            // vocab columns per i-tile (64 tiles)
#define TJ     64             // output j per block tile  (128 tiles)
#define NIB    (VOCAB / TI)   // 64 i-tiles (= segment bins)
#define NJB    (VOCAB / TJ)   // 128 j-blocks
#define NTILES (NIB * NJB)    // 8192 tiles
#define SEGCAP NTOK           // worst-case tokens per bin (adversarial-safe)
#define SMSTRIDE 68           // smT row stride in floats: 272B (16B mult, cf banks)
#define GRIDB  608            // persistent CTAs: 4 per SM x 152 SMs (single wave)
#define FINB   64             // blocks in finalize kernel

// Scratch (__device__ globals — zero-initialized at module load; no allocation)
__device__ int   g_cnt[NIB];                 // per-bin token counts
__device__ int2  g_list[NIB * SEGCAP];       // {(vocab<<16)|token, target}
__device__ float g_S[2 * VOCAB];             // double-buffered S (parity per launch)
__device__ int   g_parity;                   // which g_S buffer this launch uses
__device__ int   g_vcnt[VOCAB];              // valid-token count per vocab column
__device__ float g_logit[NTOK];              // gathered W[tgt,idx]+b[tgt] (from k_main)
__device__ float g_loss[2];                  // {sum terms, valid count}
__device__ int   g_ready;                    // scatter-complete counter (0..NIB)
__device__ int   g_done;                     // finished-block counter (finalize)

// ---------------------------------------------------------------------------
// Persistent main kernel: 608 CTAs (single wave), each loops over tiles
// tl = bid, bid+608, ... of the 64x128 (i-tile, j-tile) grid.
// Blocks 0..63 first scatter their 256-token slice into per-bin segments
//   (+ per-vocab valid counts); all blocks gate their FIRST token phase on
//   scatter completion (blocks 0..63 are resident -> no deadlock).
// Per tile: wait own TMA groups -> sync (smT reusable) -> warp-transposed W
//   tile (+bias) into smT with fused exp() column partials -> atomicAdd g_S
//   -> token phase: one cp.async.bulk 256B TMA store per token per thread
//   + predicated target-logit gather.
__global__ __launch_bounds__(256, 4)
void k_main(const int* __restrict__ idx, const int* __restrict__ tgt,
            const float* __restrict__ W, const float* __restrict__ bias,
            float* __restrict__ out) {
    __shared__ __align__(16) float smT[TI * SMSTRIDE];  // [128][68] transposed
    __shared__ float sbias[TJ];
    __shared__ float psum[8][32];
    __shared__ int   lcnt[NIB];
    __shared__ int   lbase[NIB];

    const int tid  = threadIdx.x;
    const int lane = tid & 31;
    const int wid  = tid >> 5;
    const int par  = g_parity;

    // ---- Fused scatter (blocks 0..63 only; resident in the single wave) ----
    if (blockIdx.x < NIB) {
        if (tid < NIB) lcnt[tid] = 0;
        __syncthreads();
        int t  = blockIdx.x * 256 + tid;
        int v  = idx[t];
        int tg = tgt[t];
        int bin = v >> 7;
        int lp = atomicAdd(&lcnt[bin], 1);
        if (tg >= 0) atomicAdd(&g_vcnt[v], 1);   // per-vocab valid count
        __syncthreads();
        if (tid < NIB && lcnt[tid] > 0)
            lbase[tid] = atomicAdd(&g_cnt[tid], lcnt[tid]);
        __syncthreads();
        g_list[bin * SEGCAP + lbase[bin] + lp] = make_int2((v << 16) | t, tg);
        __syncthreads();
        __threadfence();                       // release g_list/g_cnt/g_vcnt
        if (tid == 0) atomicAdd(&g_ready, 1);
    }

    bool gated = false;
    const uint32_t smT_u32 = (uint32_t)__cvta_generic_to_shared(smT);

    for (int tl = blockIdx.x; tl < NTILES; tl += GRIDB) {
        const int bi = tl & (NIB - 1);
        const int bj = tl >> 6;
        const int i0 = bi * TI;
        const int j0 = bj * TJ;
        const int base = bi * SEGCAP;

        // Previous tile's TMA reads of smT must be complete before overwrite.
        asm volatile("cp.async.bulk.wait_group 0;" ::: "memory");
        __syncthreads();   // all threads' groups drained + LDS reads done

        if (tid < TJ) sbias[tid] = bias[j0 + tid];
        __syncthreads();   // sbias ready (W-load needs it)

        // ---- Load phase: warp (ig=wid&3, jg=wid>>2) owns a 32i x 32j subtile ----
        const int ii0 = (wid & 3) * 32;
        const int jj0 = (wid >> 2) * 32;
        float acc = 0.0f;

#pragma unroll
        for (int s = 0; s < 2; s++) {
            const int jb = jj0 + s * 16;
            float v[16];
#pragma unroll
            for (int r = 0; r < 16; r++)
                v[r] = __ldcs(&W[(size_t)(j0 + jb + r) * VOCAB + i0 + ii0 + lane]);
#pragma unroll
            for (int r = 0; r < 16; r++) {
                v[r] += sbias[jb + r];
                acc += __expf(v[r]);
            }
            float* row = &smT[(ii0 + lane) * SMSTRIDE + jb];
#pragma unroll
            for (int c = 0; c < 4; c++)
                reinterpret_cast<float4*>(row)[c] =
                    make_float4(v[4 * c], v[4 * c + 1], v[4 * c + 2], v[4 * c + 3]);
        }
        psum[wid][lane] = acc;
        __syncthreads();

        // Column exp-partials -> g_S[parity] via spread-address float atomics.
        if (tid < TI) {
            int g = tid >> 5, l = tid & 31;
            atomicAdd(&g_S[par * VOCAB + i0 + tid], psum[g][l] + psum[g + 4][l]);
        }

        // Make generic-proxy STS data visible to the async (TMA) proxy.
        asm volatile("fence.proxy.async.shared::cta;" ::: "memory");

        // ---- Gate first token phase on scatter completion (acquire) ----
        if (!gated) {
            if (tid == 0) {
                while (atomicAdd(&g_ready, 0) < NIB) __nanosleep(32);
            }
            __syncthreads();
            __threadfence();
            gated = true;
        }

        const int cnt = g_cnt[bi];

        // ---- Token phase: one 256B TMA bulk store per token per thread ----
        for (int k = tid; k < cnt; k += 256) {
            int2 e = g_list[base + k];
            int t  = e.x & 0xFFFF;
            int di = (e.x >> 16) - i0;
            uint32_t saddr = smT_u32 + (uint32_t)di * (SMSTRIDE * 4);
            const float* gptr = out + (size_t)t * VOCAB + j0;
            asm volatile(
                "cp.async.bulk.global.shared::cta.bulk_group [%0], [%1], %2;"
                :: "l"(gptr), "r"(saddr), "r"(TJ * 4) : "memory");
            // Target-logit gather: tile holds W[tg, idx[t]]+b iff tg in j-range.
            unsigned dj = (unsigned)(e.y - j0);
            if (dj < TJ)
                g_logit[t] = smT[di * SMSTRIDE + dj];
        }
        asm volatile("cp.async.bulk.commit_group;" ::: "memory");
    }
    asm volatile("cp.async.bulk.wait_group 0;" ::: "memory");
}

// ---------------------------------------------------------------------------
// Finalize kernel (fully coalesced):
//   blocks 0..31  : sum_v vcnt[v]*log(S[v]) and sum_v vcnt[v] (valid count),
//                   + reset g_vcnt and other-parity g_S slice
//   blocks 32..63 : -sum_t g_logit[t] over valid tokens (+ g_cnt reset)
//   finalizer     : loss = g_loss[0]/max(g_loss[1],1), flip parity, O(1) resets
__global__ __launch_bounds__(256)
void k_fin(const int* __restrict__ tgt, float* __restrict__ out, int loss_index) {
    __shared__ float ssum[256];
    __shared__ float scnt[256];
    __shared__ int   slast;
    const int tid = threadIdx.x;
    const int b   = blockIdx.x;
    const int par = g_parity;

    float s = 0.0f, c = 0.0f;
    if (b < 32) {
        int v = b * 256 + tid;
        int vc = g_vcnt[v];
        if (vc > 0) {
            s = (float)vc * logf(g_S[par * VOCAB + v]);
            c = (float)vc;
        }
        g_vcnt[v] = 0;                       // reset (read-then-zero, own slot)
        g_S[(1 - par) * VOCAB + v] = 0.0f;   // reset other parity (untouched now)
    } else {
        int t = (b - 32) * 512 + tid;
#pragma unroll
        for (int u = 0; u < 2; u++, t += 256)
            if (tgt[t] >= 0) s -= g_logit[t];
        if (b == 32 && tid < NIB) g_cnt[tid] = 0;   // reset bin counters
    }
    ssum[tid] = s; scnt[tid] = c;
    __syncthreads();
    for (int o = 128; o > 0; o >>= 1) {
        if (tid < o) { ssum[tid] += ssum[tid + o]; scnt[tid] += scnt[tid + o]; }
        __syncthreads();
    }
    if (tid == 0) {
        atomicAdd(&g_loss[0], ssum[0]);
        atomicAdd(&g_loss[1], scnt[0]);
        __threadfence();
        slast = (atomicAdd(&g_done, 1) == FINB - 1);
    }
    __syncthreads();
    if (slast && tid == 0) {     // finalize + O(1) resets + parity flip
        out[loss_index] = g_loss[0] / fmaxf(g_loss[1], 1.0f);
        g_loss[0] = 0.0f; g_loss[1] = 0.0f;
        g_done = 0; g_ready = 0;
        g_parity = 1 - par;
    }
}

// ---------------------------------------------------------------------------
extern "C" void kernel_launch(void* const* d_in, const int* in_sizes, int n_in,
                              void* d_out, int out_size) {
    const int*   idx  = (const int*)d_in[0];
    const int*   tgt  = (const int*)d_in[1];
    const float* W    = (const float*)d_in[2];
    const float* bias = (const float*)d_in[3];
    float*       out  = (float*)d_out;

    k_main<<<GRIDB, 256>>>(idx, tgt, W, bias, out);
    k_fin<<<FINB, 256>>>(tgt, out, out_size - 1);
}

// round 16
// speedup vs baseline: 1.0754x; 1.0754x over previous
#include <cuda_runtime.h>
#include <cstdint>

// Problem constants
#define VOCAB  8192
#define NTOK   16384          // B*T = 8*2048
#define TI     128            // vocab columns per i-tile (64 tiles)
#define TJ     64             // output j per block tile  (128 tiles)
#define NIB    (VOCAB / TI)   // 64 i-tiles (= segment bins)
#define NJB    (VOCAB / TJ)   // 128 j-blocks
#define SEGCAP NTOK           // worst-case tokens per bin (adversarial-safe)
#define SMSTRIDE 68           // smT row stride in floats: 272B (16B mult, cf banks)
#define NLLB   128            // blocks in loss kernel

// Scratch (__device__ globals — zero-initialized at module load; no allocation)
__device__ int   g_cnt[NIB];                 // per-bin token counts
__device__ int2  g_list[NIB * SEGCAP];       // {(vocab<<16)|token, target}
__device__ float g_S[2 * VOCAB];             // double-buffered S (parity per launch)
__device__ int   g_parity;                   // which g_S buffer this launch uses
__device__ float g_logit[NTOK];              // gathered W[tgt,idx]+b[tgt] (from k_main)
__device__ float g_loss[2];                  // {sum_nll, count}
__device__ int   g_ready;                    // scatter-complete counter (0..NIB)
__device__ int   g_done;                     // finished-block counter (finalize)

// ---------------------------------------------------------------------------
// Main kernel: grid (64 i-tiles, 128 j-tiles), 256 threads, 5 CTAs/SM.
// Blocks with blockIdx.y==0 (linear bids 0..63 -> wave 1) first scatter their
//   256-token slice into per-bin segments, then proceed as normal tiles.
// Load phase (ungated): warp-transposed W tile (+bias) into smT[i][j] in four
//   8-row chunks (low register pressure -> 5 CTAs/SM), fused exp() column
//   partials -> float atomicAdd into g_S[parity].
// Token phase (gated on scatter completion): one cp.async.bulk 256B TMA store
//   per token per thread + predicated target-logit gather into g_logit.
__global__ __launch_bounds__(256, 5)
void k_main(const int* __restrict__ idx, const int* __restrict__ tgt,
            const float* __restrict__ W, const float* __restrict__ bias,
            float* __restrict__ out) {
    __shared__ __align__(16) float smT[TI * SMSTRIDE];  // [128][68] transposed
    __shared__ float sbias[TJ];
    __shared__ float psum[8][32];
    __shared__ int   lcnt[NIB];
    __shared__ int   lbase[NIB];

    const int i0   = blockIdx.x * TI;
    const int j0   = blockIdx.y * TJ;
    const int tid  = threadIdx.x;
    const int lane = tid & 31;
    const int wid  = tid >> 5;
    const int bi   = blockIdx.x;
    const int base = bi * SEGCAP;
    const int par  = g_parity;

    // ---- Fused scatter (first 64 linear bids only; wave-1 resident) ----
    if (blockIdx.y == 0) {
        if (tid < NIB) lcnt[tid] = 0;
        __syncthreads();
        int t  = bi * 256 + tid;
        int v  = idx[t];
        int tg = tgt[t];
        int bin = v >> 7;
        int lp = atomicAdd(&lcnt[bin], 1);
        __syncthreads();
        if (tid < NIB && lcnt[tid] > 0)
            lbase[tid] = atomicAdd(&g_cnt[tid], lcnt[tid]);
        __syncthreads();
        g_list[bin * SEGCAP + lbase[bin] + lp] = make_int2((v << 16) | t, tg);
        __syncthreads();
        __threadfence();                       // release g_list/g_cnt writes
        if (tid == 0) atomicAdd(&g_ready, 1);
    }

    if (tid < TJ) sbias[tid] = bias[j0 + tid];
    __syncthreads();   // sbias ready (W-load needs it)

    // ---- Load phase: warp (ig=wid&3, jg=wid>>2) owns a 32i x 32j subtile,
    //      processed as four 8-j chunks (low live-register count). ----
    const int ii0 = (wid & 3) * 32;
    const int jj0 = (wid >> 2) * 32;
    float acc = 0.0f;

#pragma unroll
    for (int s = 0; s < 4; s++) {
        const int jb = jj0 + s * 8;
        float v[8];
#pragma unroll
        for (int r = 0; r < 8; r++)
            v[r] = __ldcs(&W[(size_t)(j0 + jb + r) * VOCAB + i0 + ii0 + lane]);
#pragma unroll
        for (int r = 0; r < 8; r++) {
            v[r] += sbias[jb + r];
            acc += __expf(v[r]);
        }
        float* row = &smT[(ii0 + lane) * SMSTRIDE + jb];
#pragma unroll
        for (int c = 0; c < 2; c++)
            reinterpret_cast<float4*>(row)[c] =
                make_float4(v[4 * c], v[4 * c + 1], v[4 * c + 2], v[4 * c + 3]);
    }
    psum[wid][lane] = acc;
    __syncthreads();

    // Column exp-partials -> g_S[parity] via spread-address float atomics.
    if (tid < TI) {
        int g = tid >> 5, l = tid & 31;
        atomicAdd(&g_S[par * VOCAB + i0 + tid], psum[g][l] + psum[g + 4][l]);
    }

    // Make generic-proxy STS data visible to the async (TMA) proxy.
    asm volatile("fence.proxy.async.shared::cta;" ::: "memory");

    // ---- Gate token phase on scatter completion (acquire) ----
    if (tid == 0) {
        while (atomicAdd(&g_ready, 0) < NIB) __nanosleep(32);
    }
    __syncthreads();
    __threadfence();

    const int cnt = g_cnt[bi];

    // ---- Token phase: one 256B TMA bulk store per token per thread ----
    const uint32_t smT_u32 = (uint32_t)__cvta_generic_to_shared(smT);
    for (int k = tid; k < cnt; k += 256) {
        int2 e = g_list[base + k];
        int t  = e.x & 0xFFFF;
        int di = (e.x >> 16) - i0;
        uint32_t saddr = smT_u32 + (uint32_t)di * (SMSTRIDE * 4);
        const float* gptr = out + (size_t)t * VOCAB + j0;
        asm volatile(
            "cp.async.bulk.global.shared::cta.bulk_group [%0], [%1], %2;"
            :: "l"(gptr), "r"(saddr), "r"(TJ * 4) : "memory");
        // Target-logit gather: this tile holds W[tg, idx[t]]+b iff tg in j-range.
        unsigned dj = (unsigned)(e.y - j0);
        if (dj < TJ)
            g_logit[t] = smT[di * SMSTRIDE + dj];
    }
    asm volatile("cp.async.bulk.commit_group;" ::: "memory");
    asm volatile("cp.async.bulk.wait_group 0;" ::: "memory");
}

// ---------------------------------------------------------------------------
// Loss kernel: per-token NLL from g_logit + L2-hot g_S[parity], block reduce,
// fully-distributed resets (other-parity g_S slice, g_cnt slice), last-block
// finalize writes the loss and flips parity.
__global__ __launch_bounds__(128)
void k_snll(const int* __restrict__ idx, const int* __restrict__ tgt,
            float* __restrict__ out, int loss_index) {
    __shared__ float ssum[128];
    __shared__ float scnt[128];
    __shared__ int   slast;
    const int tid = threadIdx.x;
    const int b   = blockIdx.x;
    const int t   = b * 128 + tid;
    const int par = g_parity;

    int tg = tgt[t];
    float nll = 0.0f, c = 0.0f;
    if (tg >= 0) {
        nll = logf(g_S[par * VOCAB + idx[t]]) - g_logit[t];
        c = 1.0f;
    }
    ssum[tid] = nll; scnt[tid] = c;

    // Distributed resets (race-free): zero the OTHER parity's g_S slice
    // (untouched this launch) and this block's g_cnt entry (k_main is done).
    {
        int i = b * (VOCAB / NLLB) + (tid & 63);   // 64 floats per block
        if (tid < 64) g_S[(1 - par) * VOCAB + i] = 0.0f;
        if (tid == 64 && b < NIB) g_cnt[b] = 0;
    }
    __syncthreads();
    for (int o = 64; o > 0; o >>= 1) {
        if (tid < o) { ssum[tid] += ssum[tid + o]; scnt[tid] += scnt[tid + o]; }
        __syncthreads();
    }
    if (tid == 0) {
        atomicAdd(&g_loss[0], ssum[0]);
        atomicAdd(&g_loss[1], scnt[0]);
        __threadfence();
        slast = (atomicAdd(&g_done, 1) == NLLB - 1);
    }
    __syncthreads();
    if (slast && tid == 0) {     // finalize + O(1) resets + parity flip
        out[loss_index] = g_loss[0] / fmaxf(g_loss[1], 1.0f);
        g_loss[0] = 0.0f; g_loss[1] = 0.0f;
        g_done = 0; g_ready = 0;
        g_parity = 1 - par;
    }
}

// ---------------------------------------------------------------------------
extern "C" void kernel_launch(void* const* d_in, const int* in_sizes, int n_in,
                              void* d_out, int out_size) {
    const int*   idx  = (const int*)d_in[0];
    const int*   tgt  = (const int*)d_in[1];
    const float* W    = (const float*)d_in[2];
    const float* bias = (const float*)d_in[3];
    float*       out  = (float*)d_out;

    k_main<<<dim3(NIB, NJB), 256>>>(idx, tgt, W, bias, out);
    k_snll<<<NLLB, 128>>>(idx, tgt, out, out_size - 1);
}

// round 17
// speedup vs baseline: 1.0756x; 1.0002x over previous
#include <cuda_runtime.h>
#include <cstdint>

// Problem constants
#define VOCAB  8192
#define NTOK   16384          // B*T = 8*2048
#define TI     128            // vocab columns per i-tile (64 tiles)
#define TJ     64             // output j per block tile  (128 tiles)
#define NIB    (VOCAB / TI)   // 64 i-tiles (= segment bins)
#define NJB    (VOCAB / TJ)   // 128 j-blocks
#define SEGCAP NTOK           // worst-case tokens per bin (adversarial-safe)
#define SMSTRIDE 68           // smT row stride in floats: 272B (16B mult, cf banks)
#define NLLB   128            // blocks in loss kernel

// Scratch (__device__ globals — zero-initialized at module load; no allocation)
__device__ int   g_cnt[NIB];                 // per-bin token counts
__device__ int2  g_list[NIB * SEGCAP];       // {(vocab<<16)|token, target}
__device__ float g_S[2 * VOCAB];             // double-buffered S (parity per launch)
__device__ int   g_parity;                   // which g_S buffer this launch uses
__device__ float g_logit[NTOK];              // gathered W[tgt,idx]+b[tgt] (from k_main)
__device__ float g_loss[2];                  // {sum_nll, count}
__device__ int   g_ready;                    // scatter-complete counter (0..NIB)
__device__ int   g_done;                     // finished-block counter (finalize)

// ---------------------------------------------------------------------------
// Main kernel: grid (64 i-tiles, 128 j-tiles), 256 threads, 6 CTAs/SM.
// Blocks with blockIdx.y==0 (linear bids 0..63 -> wave 1) first scatter their
//   256-token slice into per-bin segments, then proceed as normal tiles.
// Load phase (ungated): warp-transposed W tile (+bias) into smT[i][j] in four
//   8-row chunks with early exp-fusion (short liveness -> 42 regs, 6 CTAs/SM),
//   fused exp() column partials -> float atomicAdd into g_S[parity].
// Token phase (gated on scatter completion): one cp.async.bulk 256B TMA store
//   per token per thread + predicated target-logit gather into g_logit.
__global__ __launch_bounds__(256, 6)
void k_main(const int* __restrict__ idx, const int* __restrict__ tgt,
            const float* __restrict__ W, const float* __restrict__ bias,
            float* __restrict__ out) {
    __shared__ __align__(16) float smT[TI * SMSTRIDE];  // [128][68] transposed
    __shared__ float sbias[TJ];
    __shared__ float psum[8][32];
    __shared__ int   lcnt[NIB];

    const int i0   = blockIdx.x * TI;
    const int j0   = blockIdx.y * TJ;
    const int tid  = threadIdx.x;
    const int lane = tid & 31;
    const int wid  = tid >> 5;
    const int bi   = blockIdx.x;
    const int base = bi * SEGCAP;
    const int par  = g_parity;

    // ---- Fused scatter (first 64 linear bids only; wave-1 resident) ----
    if (blockIdx.y == 0) {
        if (tid < NIB) lcnt[tid] = 0;
        __syncthreads();
        int t  = bi * 256 + tid;
        int v  = idx[t];
        int tg = tgt[t];
        int bin = v >> 7;
        int lp = atomicAdd(&lcnt[bin], 1);
        __syncthreads();
        // Convert local slot to global slot: lcnt[bin] now = block-local total.
        int gb = 0;
        if (tid < NIB && lcnt[tid] > 0)
            gb = atomicAdd(&g_cnt[tid], lcnt[tid]);
        __syncthreads();
        if (tid < NIB) lcnt[tid] = gb;     // reuse lcnt as global base
        __syncthreads();
        g_list[bin * SEGCAP + lcnt[bin] + lp] = make_int2((v << 16) | t, tg);
        __syncthreads();
        __threadfence();                   // release g_list/g_cnt writes
        if (tid == 0) atomicAdd(&g_ready, 1);
    }

    if (tid < TJ) sbias[tid] = bias[j0 + tid];
    __syncthreads();   // sbias ready (W-load needs it)

    // ---- Load phase: warp (ig=wid&3, jg=wid>>2) owns a 32i x 32j subtile,
    //      processed as four 8-j chunks (low live-register count). ----
    const int ii0 = (wid & 3) * 32;
    const int jj0 = (wid >> 2) * 32;
    float acc = 0.0f;

#pragma unroll
    for (int s = 0; s < 4; s++) {
        const int jb = jj0 + s * 8;
        float v[8];
#pragma unroll
        for (int r = 0; r < 8; r++)
            v[r] = __ldcs(&W[(size_t)(j0 + jb + r) * VOCAB + i0 + ii0 + lane]);
#pragma unroll
        for (int r = 0; r < 8; r++) {
            v[r] += sbias[jb + r];
            acc += __expf(v[r]);
        }
        float* row = &smT[(ii0 + lane) * SMSTRIDE + jb];
#pragma unroll
        for (int c = 0; c < 2; c++)
            reinterpret_cast<float4*>(row)[c] =
                make_float4(v[4 * c], v[4 * c + 1], v[4 * c + 2], v[4 * c + 3]);
    }
    psum[wid][lane] = acc;
    __syncthreads();

    // Column exp-partials -> g_S[parity] via spread-address float atomics.
    if (tid < TI) {
        int g = tid >> 5, l = tid & 31;
        atomicAdd(&g_S[par * VOCAB + i0 + tid], psum[g][l] + psum[g + 4][l]);
    }

    // Make generic-proxy STS data visible to the async (TMA) proxy.
    asm volatile("fence.proxy.async.shared::cta;" ::: "memory");

    // ---- Gate token phase on scatter completion (acquire) ----
    if (tid == 0) {
        while (atomicAdd(&g_ready, 0) < NIB) __nanosleep(32);
    }
    __syncthreads();
    __threadfence();

    const int cnt = g_cnt[bi];

    // ---- Token phase: one 256B TMA bulk store per token per thread ----
    const uint32_t smT_u32 = (uint32_t)__cvta_generic_to_shared(smT);
    for (int k = tid; k < cnt; k += 256) {
        int2 e = g_list[base + k];
        int t  = e.x & 0xFFFF;
        int di = (e.x >> 16) - i0;
        uint32_t saddr = smT_u32 + (uint32_t)di * (SMSTRIDE * 4);
        const float* gptr = out + (size_t)t * VOCAB + j0;
        asm volatile(
            "cp.async.bulk.global.shared::cta.bulk_group [%0], [%1], %2;"
            :: "l"(gptr), "r"(saddr), "r"(TJ * 4) : "memory");
        // Target-logit gather: this tile holds W[tg, idx[t]]+b iff tg in j-range.
        unsigned dj = (unsigned)(e.y - j0);
        if (dj < TJ)
            g_logit[t] = smT[di * SMSTRIDE + dj];
    }
    asm volatile("cp.async.bulk.commit_group;" ::: "memory");
    asm volatile("cp.async.bulk.wait_group 0;" ::: "memory");
}

// ---------------------------------------------------------------------------
// Loss kernel: per-token NLL from g_logit + L2-hot g_S[parity], block reduce,
// fully-distributed resets (other-parity g_S slice, g_cnt slice), last-block
// finalize writes the loss and flips parity.
__global__ __launch_bounds__(128)
void k_snll(const int* __restrict__ idx, const int* __restrict__ tgt,
            float* __restrict__ out, int loss_index) {
    __shared__ float ssum[128];
    __shared__ float scnt[128];
    __shared__ int   slast;
    const int tid = threadIdx.x;
    const int b   = blockIdx.x;
    const int t   = b * 128 + tid;
    const int par = g_parity;

    int tg = tgt[t];
    float nll = 0.0f, c = 0.0f;
    if (tg >= 0) {
        nll = logf(g_S[par * VOCAB + idx[t]]) - g_logit[t];
        c = 1.0f;
    }
    ssum[tid] = nll; scnt[tid] = c;

    // Distributed resets (race-free): zero the OTHER parity's g_S slice
    // (untouched this launch) and this block's g_cnt entry (k_main is done).
    {
        int i = b * (VOCAB / NLLB) + (tid & 63);   // 64 floats per block
        if (tid < 64) g_S[(1 - par) * VOCAB + i] = 0.0f;
        if (tid == 64 && b < NIB) g_cnt[b] = 0;
    }
    __syncthreads();
    for (int o = 64; o > 0; o >>= 1) {
        if (tid < o) { ssum[tid] += ssum[tid + o]; scnt[tid] += scnt[tid + o]; }
        __syncthreads();
    }
    if (tid == 0) {
        atomicAdd(&g_loss[0], ssum[0]);
        atomicAdd(&g_loss[1], scnt[0]);
        __threadfence();
        slast = (atomicAdd(&g_done, 1) == NLLB - 1);
    }
    __syncthreads();
    if (slast && tid == 0) {     // finalize + O(1) resets + parity flip
        out[loss_index] = g_loss[0] / fmaxf(g_loss[1], 1.0f);
        g_loss[0] = 0.0f; g_loss[1] = 0.0f;
        g_done = 0; g_ready = 0;
        g_parity = 1 - par;
    }
}

// ---------------------------------------------------------------------------
extern "C" void kernel_launch(void* const* d_in, const int* in_sizes, int n_in,
                              void* d_out, int out_size) {
    const int*   idx  = (const int*)d_in[0];
    const int*   tgt  = (const int*)d_in[1];
    const float* W    = (const float*)d_in[2];
    const float* bias = (const float*)d_in[3];
    float*       out  = (float*)d_out;

    k_main<<<dim3(NIB, NJB), 256>>>(idx, tgt, W, bias, out);
    k_snll<<<NLLB, 128>>>(idx, tgt, out, out_size - 1);
}